// round 9
// baseline (speedup 1.0000x reference)
#include <cuda_runtime.h>
#include <cuda_fp16.h>
#include <cstdint>

// Problem constants
#define DMODEL 1024
#define NHEADS 16
#define DHEAD  64
#define SQ_TOT 6144   // per batch
#define SK_TOT 1024
#define BATCH  2

// Scratch (allocation-free rule: __device__ globals), all fp16.
__device__ __half g_xH[BATCH * SQ_TOT * DMODEL];
__device__ __half g_cH[BATCH * SK_TOT * DMODEL];
__device__ __half g_wqH[DMODEL * DMODEL];
__device__ __half g_wkH[DMODEL * DMODEL];
__device__ __half g_wvH[DMODEL * DMODEL];
__device__ __half g_woH[DMODEL * DMODEL];
__device__ __half g_Qh[BATCH * SQ_TOT * DMODEL];   // pre-scaled by 0.125*log2(e)
__device__ __half g_Kh[BATCH * SK_TOT * DMODEL];
__device__ __half g_Vh[BATCH * NHEADS * DHEAD * SK_TOT]; // [b][h][d][key]
__device__ __half g_Ah[BATCH * SQ_TOT * DMODEL];

__device__ __forceinline__ uint32_t smem_u32(const void* p) {
    uint32_t a;
    asm("{ .reg .u64 t; cvta.to.shared.u64 t, %1; cvt.u32.u64 %0, t; }"
        : "=r"(a) : "l"(p));
    return a;
}

__device__ __forceinline__ uint32_t packh2(float a, float b) {
    __half2 h = __floats2half2_rn(a, b);
    return *reinterpret_cast<uint32_t*>(&h);
}

#define CP16(dst, src) \
    asm volatile("cp.async.cg.shared.global [%0], [%1], 16;" :: "r"(dst), "l"(src))
#define CP_COMMIT() asm volatile("cp.async.commit_group;" ::: "memory")
#define CP_WAIT(n)  asm volatile("cp.async.wait_group %0;" :: "n"(n) : "memory")

#define LDSM_X4(r0, r1, r2, r3, addr) \
    asm volatile("ldmatrix.sync.aligned.m8n8.x4.shared.b16 {%0,%1,%2,%3}, [%4];" \
        : "=r"(r0), "=r"(r1), "=r"(r2), "=r"(r3) : "r"(addr))

#define MMA_F16(d, a0, a1, a2, a3, b0, b1) \
    asm volatile( \
        "mma.sync.aligned.m16n8k16.row.col.f32.f16.f16.f32 " \
        "{%0,%1,%2,%3}, {%4,%5,%6,%7}, {%8,%9}, {%0,%1,%2,%3};" \
        : "+f"((d)[0]), "+f"((d)[1]), "+f"((d)[2]), "+f"((d)[3]) \
        : "r"(a0), "r"(a1), "r"(a2), "r"(a3), "r"(b0), "r"(b1))

// ===========================================================================
// fp32 -> fp16 conversion
// ===========================================================================
__global__ void cvt_f16(const float* __restrict__ in, __half* __restrict__ out, int n)
{
    int i = (blockIdx.x * blockDim.x + threadIdx.x) * 8;
    if (i < n) {
        float4 a = *(const float4*)(in + i);
        float4 b = *(const float4*)(in + i + 4);
        __half2* o = (__half2*)(out + i);
        o[0] = __floats2half2_rn(a.x, a.y);
        o[1] = __floats2half2_rn(a.z, a.w);
        o[2] = __floats2half2_rn(b.x, b.y);
        o[3] = __floats2half2_rn(b.z, b.w);
    }
}

__global__ void cvt_f16x4(
    const float* __restrict__ i0, __half* __restrict__ o0,
    const float* __restrict__ i1, __half* __restrict__ o1,
    const float* __restrict__ i2, __half* __restrict__ o2,
    const float* __restrict__ i3, __half* __restrict__ o3, int n)
{
    const float* in; __half* out;
    switch (blockIdx.y) {
        case 0: in = i0; out = o0; break;
        case 1: in = i1; out = o1; break;
        case 2: in = i2; out = o2; break;
        default: in = i3; out = o3; break;
    }
    int i = (blockIdx.x * blockDim.x + threadIdx.x) * 8;
    if (i < n) {
        float4 a = *(const float4*)(in + i);
        float4 b = *(const float4*)(in + i + 4);
        __half2* o = (__half2*)(out + i);
        o[0] = __floats2half2_rn(a.x, a.y);
        o[1] = __floats2half2_rn(a.z, a.w);
        o[2] = __floats2half2_rn(b.x, b.y);
        o[3] = __floats2half2_rn(b.z, b.w);
    }
}

// ===========================================================================
// Shared GEMM mainloop: CTA 128x128, 128 threads = 4 warps (2M x 2N),
// warp tile 64x64 (4 m16 x 8 n8), KC=32, 3-stage cp.async, 1 barrier/chunk.
// K fixed = DMODEL = 1024. acc[4][8][4].
// ===========================================================================
#define KCH 32
#define SAH 40
#define NST 3
#define GSTAGE (128 * SAH)
#define GP_SMEM (2 * NST * GSTAGE * 2)

struct GemmFrag {
    int wm, wn;          // warp tile offsets
    uint32_t sA0, sB0;   // cp.async dst base (per-thread)
    uint32_t aBase, bBase; // ldmatrix base (per-lane)
};

__device__ __forceinline__ void gemm_setup(GemmFrag& f, __half* As, __half* Bs)
{
    const int tid = threadIdx.x;
    const int wid = tid >> 5;
    const int lane = tid & 31;
    f.wm = (wid & 1) * 64;
    f.wn = (wid >> 1) * 64;
    // cp.async: row = tid, 4 x 16B chunks (32 halves)
    f.sA0 = smem_u32(As) + tid * SAH * 2;
    f.sB0 = smem_u32(Bs) + tid * SAH * 2;
    const int arow = (lane & 7) + ((lane >> 3) & 1) * 8;
    const int acol = (lane >> 4) * 8;
    const int brow = (lane & 7) + (lane >> 4) * 8;
    const int bcol = ((lane >> 3) & 1) * 8;
    f.aBase = smem_u32(As) + ((f.wm + arow) * SAH + acol) * 2;
    f.bBase = smem_u32(Bs) + ((f.wn + brow) * SAH + bcol) * 2;
}

// Ag/Bg: global row pointers for this thread's cp.async row (row = tid).
__device__ __forceinline__ void gemm_mainloop(
    const GemmFrag& f, const __half* Ag, const __half* Bg, float acc[4][8][4])
{
#pragma unroll
    for (int i = 0; i < 4; i++)
#pragma unroll
        for (int j = 0; j < 8; j++)
#pragma unroll
            for (int r = 0; r < 4; r++) acc[i][j][r] = 0.0f;

    const uint32_t stB = GSTAGE * 2;
    const int NC = DMODEL / KCH;   // 32

#pragma unroll
    for (int c = 0; c < NST - 1; c++) {
#pragma unroll
        for (int i = 0; i < 4; i++) {
            CP16(f.sA0 + c * stB + i * 16, Ag + (size_t)c * KCH + i * 8);
            CP16(f.sB0 + c * stB + i * 16, Bg + (size_t)c * KCH + i * 8);
        }
        CP_COMMIT();
    }

    for (int c = 0; c < NC; c++) {
        const int st = c % NST;
        CP_WAIT(NST - 2);
        __syncthreads();

        {
            const int cn = c + NST - 1;
            if (cn < NC) {
                const int sn = cn % NST;
#pragma unroll
                for (int i = 0; i < 4; i++) {
                    CP16(f.sA0 + sn * stB + i * 16, Ag + (size_t)cn * KCH + i * 8);
                    CP16(f.sB0 + sn * stB + i * 16, Bg + (size_t)cn * KCH + i * 8);
                }
            }
            CP_COMMIT();
        }

        const uint32_t aSt = f.aBase + st * stB;
        const uint32_t bSt = f.bBase + st * stB;
#pragma unroll
        for (int ks = 0; ks < 2; ks++) {
            uint32_t a[4][4];
#pragma unroll
            for (int mt = 0; mt < 4; mt++)
                LDSM_X4(a[mt][0], a[mt][1], a[mt][2], a[mt][3],
                        aSt + (mt * 16 * SAH + ks * 16) * 2);
#pragma unroll
            for (int p = 0; p < 4; p++) {
                uint32_t b0, b1, b2, b3;
                LDSM_X4(b0, b1, b2, b3, bSt + (p * 16 * SAH + ks * 16) * 2);
#pragma unroll
                for (int mt = 0; mt < 4; mt++) {
                    MMA_F16(acc[mt][2 * p],     a[mt][0], a[mt][1], a[mt][2], a[mt][3], b0, b1);
                    MMA_F16(acc[mt][2 * p + 1], a[mt][0], a[mt][1], a[mt][2], a[mt][3], b2, b3);
                }
            }
        }
    }
}

// ===========================================================================
// Merged Q/K/V projection. 1D grid of 1024 CTAs:
//   [0,768):   Q = x @ Wq^T * qscale          (M=12288, N=1024)
//   [768,896): K = ctx @ Wk^T                 (M=2048,  N=1024)
//   [896,1024):V = ctx @ Wv^T  -> [b][h][d][key]
// ===========================================================================
__global__ __launch_bounds__(128) void proj_qkv(
    const __half* __restrict__ xH, const __half* __restrict__ cH,
    const __half* __restrict__ wq, const __half* __restrict__ wk,
    const __half* __restrict__ wv,
    __half* __restrict__ Qo, __half* __restrict__ Ko, __half* __restrict__ Vo,
    float qscale)
{
    extern __shared__ __half sh[];
    __half* As = sh;
    __half* Bs = sh + NST * GSTAGE;

    const int bx = blockIdx.x;
    const int tid = threadIdx.x;
    const int lane = tid & 31;
    const int g = lane >> 2;
    const int t = lane & 3;

    const __half* A;
    const __half* B;
    int bm, bn, job;   // job: 0=Q, 1=K, 2=V
    if (bx < 768) {
        A = xH; B = wq; bm = (bx >> 3) * 128; bn = (bx & 7) * 128; job = 0;
    } else {
        const int r = bx - 768;
        A = cH; bm = (r >> 4) * 128;
        const int nb = r & 15;
        if (nb < 8) { B = wk; bn = nb * 128; job = 1; }
        else        { B = wv; bn = (nb - 8) * 128; job = 2; }
    }

    GemmFrag f;
    gemm_setup(f, As, Bs);

    float acc[4][8][4];
    gemm_mainloop(f, A + (size_t)(bm + tid) * DMODEL,
                     B + (size_t)(bn + tid) * DMODEL, acc);

#pragma unroll
    for (int mt = 0; mt < 4; mt++) {
#pragma unroll
        for (int nt = 0; nt < 8; nt++) {
            const int row = bm + f.wm + mt * 16 + g;
            const int col = bn + f.wn + nt * 8 + 2 * t;
            float c0 = acc[mt][nt][0], c1 = acc[mt][nt][1];
            float c2 = acc[mt][nt][2], c3 = acc[mt][nt][3];
            if (job == 0) {
                *(__half2*)&Qo[(size_t)row * DMODEL + col] =
                    __floats2half2_rn(c0 * qscale, c1 * qscale);
                *(__half2*)&Qo[(size_t)(row + 8) * DMODEL + col] =
                    __floats2half2_rn(c2 * qscale, c3 * qscale);
            } else if (job == 1) {
                *(__half2*)&Ko[(size_t)row * DMODEL + col] = __floats2half2_rn(c0, c1);
                *(__half2*)&Ko[(size_t)(row + 8) * DMODEL + col] = __floats2half2_rn(c2, c3);
            } else {
                const int b = row >> 10, key = row & 1023;
                const int h = col >> 6, d = col & 63;
                __half* base = Vo + ((size_t)((b * NHEADS + h) * DHEAD + d)) * SK_TOT;
                base[key]              = __float2half(c0);
                base[SK_TOT + key]     = __float2half(c1);
                base[key + 8]          = __float2half(c2);
                base[SK_TOT + key + 8] = __float2half(c3);
            }
        }
    }
}

// ===========================================================================
// Output projection: out = A @ Wo^T + bias (fp32 out). Grid (8, 96), 128 thr.
// ===========================================================================
__global__ __launch_bounds__(128) void gemm_out(
    const __half* __restrict__ A, const __half* __restrict__ B,
    float* __restrict__ Cf, const float* __restrict__ bias)
{
    extern __shared__ __half sh[];
    __half* As = sh;
    __half* Bs = sh + NST * GSTAGE;

    const int tid = threadIdx.x;
    const int lane = tid & 31;
    const int g = lane >> 2;
    const int t = lane & 3;
    const int bm = blockIdx.y * 128;
    const int bn = blockIdx.x * 128;

    GemmFrag f;
    gemm_setup(f, As, Bs);

    float acc[4][8][4];
    gemm_mainloop(f, A + (size_t)(bm + tid) * DMODEL,
                     B + (size_t)(bn + tid) * DMODEL, acc);

#pragma unroll
    for (int mt = 0; mt < 4; mt++) {
#pragma unroll
        for (int nt = 0; nt < 8; nt++) {
            const int row = bm + f.wm + mt * 16 + g;
            const int col = bn + f.wn + nt * 8 + 2 * t;
            float2 bv = *(const float2*)&bias[col];
            *(float2*)&Cf[(size_t)row * DMODEL + col] =
                make_float2(acc[mt][nt][0] + bv.x, acc[mt][nt][1] + bv.y);
            *(float2*)&Cf[(size_t)(row + 8) * DMODEL + col] =
                make_float2(acc[mt][nt][2] + bv.x, acc[mt][nt][3] + bv.y);
        }
    }
}

// ===========================================================================
// Flash attention: fp16 mma, P-in-registers, Q fragments hoisted,
// 3-buffer K/V cp.async pipeline, ONE barrier per key tile. (unchanged R8)
// ===========================================================================
#define AS 72
#define NKT (SK_TOT / 64)
#define NBUF 3
#define ATT_SMEM ((128 + 2 * NBUF * 64) * AS * 2)

__global__ __launch_bounds__(256) void attn_f16(
    const __half* __restrict__ Q, const __half* __restrict__ K,
    const __half* __restrict__ V, __half* __restrict__ O)
{
    extern __shared__ __half sma[];
    __half* sQ  = sma;
    __half* sKb = sQ + 128 * AS;
    __half* sVb = sKb + NBUF * 64 * AS;
    const uint32_t bufBytes = 64 * AS * 2;

    const int b = blockIdx.z;
    const int h = blockIdx.y;
    const int qt = blockIdx.x;

    const int tid = threadIdx.x;
    const int wid = tid >> 5;
    const int lane = tid & 31;
    const int g = lane >> 2;
    const int t = lane & 3;

    const uint32_t sQa = smem_u32(sQ);
    const uint32_t sKa = smem_u32(sKb);
    const uint32_t sVa = smem_u32(sVb);

    {
        const int row = tid >> 1, c0 = (tid & 1) * 4;
        const __half* qg = Q + (size_t)(b * SQ_TOT + qt * 128 + row) * DMODEL
                             + h * DHEAD + c0 * 8;
        const uint32_t qd = sQa + (row * AS + c0 * 8) * 2;
#pragma unroll
        for (int i = 0; i < 4; i++) CP16(qd + i * 16, qg + i * 8);
    }

    const int lrow = tid >> 2;
    const int lc = (tid & 3) * 2;
    const __half* kgB = K + (size_t)(b * SK_TOT + lrow) * DMODEL + h * DHEAD + lc * 8;
    const __half* vgB = V + ((size_t)((b * NHEADS + h) * DHEAD + lrow)) * SK_TOT + lc * 8;
    const uint32_t kd0 = sKa + (lrow * AS + lc * 8) * 2;
    const uint32_t vd0 = sVa + (lrow * AS + lc * 8) * 2;

#define ISSUE_KV(kt, buf) do { \
        const __half* kg_ = kgB + (size_t)(kt) * 64 * DMODEL; \
        const __half* vg_ = vgB + (kt) * 64; \
        const uint32_t kd_ = kd0 + (buf) * bufBytes; \
        const uint32_t vd_ = vd0 + (buf) * bufBytes; \
        CP16(kd_, kg_);      CP16(kd_ + 16, kg_ + 8); \
        CP16(vd_, vg_);      CP16(vd_ + 16, vg_ + 8); \
    } while (0)

    ISSUE_KV(0, 0); CP_COMMIT();
    ISSUE_KV(1, 1); CP_COMMIT();

    const int arow = (lane & 7) + ((lane >> 3) & 1) * 8;
    const int acol = (lane >> 4) * 8;
    const int brow = (lane & 7) + (lane >> 4) * 8;
    const int bcol = ((lane >> 3) & 1) * 8;
    const uint32_t aQ = sQa + ((wid * 16 + arow) * AS + acol) * 2;
    const uint32_t bK0 = sKa + (brow * AS + bcol) * 2;
    const uint32_t bV0 = sVa + (brow * AS + bcol) * 2;

    CP_WAIT(1);
    __syncthreads();
    uint32_t qf[4][4];
#pragma unroll
    for (int ks = 0; ks < 4; ks++)
        LDSM_X4(qf[ks][0], qf[ks][1], qf[ks][2], qf[ks][3], aQ + ks * 32);

    float m0 = -1e30f, m1 = -1e30f, l0 = 0.0f, l1 = 0.0f;
    float o[8][4];
#pragma unroll
    for (int dt = 0; dt < 8; dt++)
#pragma unroll
        for (int r = 0; r < 4; r++) o[dt][r] = 0.0f;

    for (int kt = 0; kt < NKT; kt++) {
        if (kt > 0) {
            CP_WAIT(1);
            __syncthreads();
        }
        if (kt + 2 < NKT) ISSUE_KV(kt + 2, (kt + 2) % NBUF);
        CP_COMMIT();

        const uint32_t bOff = (kt % NBUF) * bufBytes;
        const uint32_t bK = bK0 + bOff;
        const uint32_t bV = bV0 + bOff;

        float s[8][4];
#pragma unroll
        for (int nt = 0; nt < 8; nt++)
#pragma unroll
            for (int r = 0; r < 4; r++) s[nt][r] = 0.0f;

#pragma unroll
        for (int ks = 0; ks < 4; ks++) {
#pragma unroll
            for (int p = 0; p < 4; p++) {
                uint32_t b0, b1, b2, b3;
                LDSM_X4(b0, b1, b2, b3, bK + (p * 16 * AS + ks * 16) * 2);
                MMA_F16(s[2 * p],     qf[ks][0], qf[ks][1], qf[ks][2], qf[ks][3], b0, b1);
                MMA_F16(s[2 * p + 1], qf[ks][0], qf[ks][1], qf[ks][2], qf[ks][3], b2, b3);
            }
        }

        float ml0 = -1e30f, ml1 = -1e30f;
#pragma unroll
        for (int nt = 0; nt < 8; nt++) {
            ml0 = fmaxf(ml0, fmaxf(s[nt][0], s[nt][1]));
            ml1 = fmaxf(ml1, fmaxf(s[nt][2], s[nt][3]));
        }
        ml0 = fmaxf(ml0, __shfl_xor_sync(0xffffffffu, ml0, 1));
        ml0 = fmaxf(ml0, __shfl_xor_sync(0xffffffffu, ml0, 2));
        ml1 = fmaxf(ml1, __shfl_xor_sync(0xffffffffu, ml1, 1));
        ml1 = fmaxf(ml1, __shfl_xor_sync(0xffffffffu, ml1, 2));

        const float mn0 = fmaxf(m0, ml0);
        const float mn1 = fmaxf(m1, ml1);
        const float al0 = exp2f(m0 - mn0);
        const float al1 = exp2f(m1 - mn1);
        m0 = mn0; m1 = mn1;

        float rs0 = 0.0f, rs1 = 0.0f;
        uint32_t pa[4][4];
#pragma unroll
        for (int c = 0; c < 4; c++) {
            float p00 = exp2f(s[2 * c][0] - mn0);
            float p01 = exp2f(s[2 * c][1] - mn0);
            float p02 = exp2f(s[2 * c][2] - mn1);
            float p03 = exp2f(s[2 * c][3] - mn1);
            float p10 = exp2f(s[2 * c + 1][0] - mn0);
            float p11 = exp2f(s[2 * c + 1][1] - mn0);
            float p12 = exp2f(s[2 * c + 1][2] - mn1);
            float p13 = exp2f(s[2 * c + 1][3] - mn1);
            rs0 += p00 + p01 + p10 + p11;
            rs1 += p02 + p03 + p12 + p13;
            pa[c][0] = packh2(p00, p01);
            pa[c][1] = packh2(p02, p03);
            pa[c][2] = packh2(p10, p11);
            pa[c][3] = packh2(p12, p13);
        }
        rs0 += __shfl_xor_sync(0xffffffffu, rs0, 1);
        rs0 += __shfl_xor_sync(0xffffffffu, rs0, 2);
        rs1 += __shfl_xor_sync(0xffffffffu, rs1, 1);
        rs1 += __shfl_xor_sync(0xffffffffu, rs1, 2);
        l0 = l0 * al0 + rs0;
        l1 = l1 * al1 + rs1;
#pragma unroll
        for (int dt = 0; dt < 8; dt++) {
            o[dt][0] *= al0; o[dt][1] *= al0;
            o[dt][2] *= al1; o[dt][3] *= al1;
        }

#pragma unroll
        for (int c = 0; c < 4; c++) {
#pragma unroll
            for (int p = 0; p < 4; p++) {
                uint32_t b0, b1, b2, b3;
                LDSM_X4(b0, b1, b2, b3, bV + (p * 16 * AS + c * 16) * 2);
                MMA_F16(o[2 * p],     pa[c][0], pa[c][1], pa[c][2], pa[c][3], b0, b1);
                MMA_F16(o[2 * p + 1], pa[c][0], pa[c][1], pa[c][2], pa[c][3], b2, b3);
            }
        }
    }

    const float inv0 = 1.0f / l0;
    const float inv1 = 1.0f / l1;
    const size_t row0 = (size_t)(b * SQ_TOT + qt * 128 + wid * 16 + g);
    __half* o0 = O + row0 * DMODEL + h * DHEAD + 2 * t;
    __half* o1 = o0 + 8 * DMODEL;
#pragma unroll
    for (int dt = 0; dt < 8; dt++) {
        *(__half2*)(o0 + dt * 8) = __floats2half2_rn(o[dt][0] * inv0, o[dt][1] * inv0);
        *(__half2*)(o1 + dt * 8) = __floats2half2_rn(o[dt][2] * inv1, o[dt][3] * inv1);
    }
}

// ===========================================================================
extern "C" void kernel_launch(void* const* d_in, const int* in_sizes, int n_in,
                              void* d_out, int out_size)
{
    const float* x   = (const float*)d_in[0];
    const float* ctx = (const float*)d_in[1];
    const float* Wq  = (const float*)d_in[2];
    const float* Wk  = (const float*)d_in[3];
    const float* Wv  = (const float*)d_in[4];
    const float* Wo  = (const float*)d_in[5];
    const float* bo  = (const float*)d_in[6];
    float* out = (float*)d_out;

    __half *xH, *cH, *wqH, *wkH, *wvH, *woH, *qh, *kh, *vh, *ah;
    cudaGetSymbolAddress((void**)&xH,  g_xH);
    cudaGetSymbolAddress((void**)&cH,  g_cH);
    cudaGetSymbolAddress((void**)&wqH, g_wqH);
    cudaGetSymbolAddress((void**)&wkH, g_wkH);
    cudaGetSymbolAddress((void**)&wvH, g_wvH);
    cudaGetSymbolAddress((void**)&woH, g_woH);
    cudaGetSymbolAddress((void**)&qh,  g_Qh);
    cudaGetSymbolAddress((void**)&kh,  g_Kh);
    cudaGetSymbolAddress((void**)&vh,  g_Vh);
    cudaGetSymbolAddress((void**)&ah,  g_Ah);

    cudaFuncSetAttribute(proj_qkv,
                         cudaFuncAttributeMaxDynamicSharedMemorySize, GP_SMEM);
    cudaFuncSetAttribute(gemm_out,
                         cudaFuncAttributeMaxDynamicSharedMemorySize, GP_SMEM);
    cudaFuncSetAttribute(attn_f16,
                         cudaFuncAttributeMaxDynamicSharedMemorySize, ATT_SMEM);

    const int M_Q = BATCH * SQ_TOT;   // 12288
    const int M_KV = BATCH * SK_TOT;  // 2048
    const int NW = DMODEL * DMODEL;

    cvt_f16<<<(M_Q * DMODEL / 8 + 255) / 256, 256>>>(x, xH, M_Q * DMODEL);
    cvt_f16<<<(M_KV * DMODEL / 8 + 255) / 256, 256>>>(ctx, cH, M_KV * DMODEL);
    cvt_f16x4<<<dim3((NW / 8 + 255) / 256, 4), 256>>>(
        Wq, wqH, Wk, wkH, Wv, wvH, Wo, woH, NW);

    const float QSCALE = 0.125f * 1.44269504088896341f;  // 1/sqrt(64) * log2(e)

    // merged Q/K/V projection: 768 Q-blocks + 256 KV-blocks
    proj_qkv<<<1024, 128, GP_SMEM>>>(xH, cH, wqH, wkH, wvH, qh, kh, vh, QSCALE);

    attn_f16<<<dim3(SQ_TOT / 128, NHEADS, BATCH), 256, ATT_SMEM>>>(qh, kh, vh, ah);

    gemm_out<<<dim3(8, 96), 128, GP_SMEM>>>(ah, woH, out, bo);
}

// round 10
// speedup vs baseline: 1.1565x; 1.1565x over previous
#include <cuda_runtime.h>
#include <cuda_fp16.h>
#include <cstdint>

// Problem constants
#define DMODEL 1024
#define NHEADS 16
#define DHEAD  64
#define SQ_TOT 6144   // per batch
#define SK_TOT 1024
#define BATCH  2

// Scratch (allocation-free rule: __device__ globals), all fp16.
__device__ __half g_xH[BATCH * SQ_TOT * DMODEL];
__device__ __half g_cH[BATCH * SK_TOT * DMODEL];
__device__ __half g_wqH[DMODEL * DMODEL];
__device__ __half g_wkH[DMODEL * DMODEL];
__device__ __half g_wvH[DMODEL * DMODEL];
__device__ __half g_woH[DMODEL * DMODEL];
__device__ __half g_Qh[BATCH * SQ_TOT * DMODEL];   // pre-scaled by 0.125*log2(e)
__device__ __half g_Kh[BATCH * SK_TOT * DMODEL];
__device__ __half g_Vh[BATCH * NHEADS * DHEAD * SK_TOT]; // [b][h][d][key]
__device__ __half g_Ah[BATCH * SQ_TOT * DMODEL];

__device__ __forceinline__ uint32_t smem_u32(const void* p) {
    uint32_t a;
    asm("{ .reg .u64 t; cvta.to.shared.u64 t, %1; cvt.u32.u64 %0, t; }"
        : "=r"(a) : "l"(p));
    return a;
}

__device__ __forceinline__ uint32_t packh2(float a, float b) {
    __half2 h = __floats2half2_rn(a, b);
    return *reinterpret_cast<uint32_t*>(&h);
}

#define CP16(dst, src) \
    asm volatile("cp.async.cg.shared.global [%0], [%1], 16;" :: "r"(dst), "l"(src))
#define CP_COMMIT() asm volatile("cp.async.commit_group;" ::: "memory")
#define CP_WAIT(n)  asm volatile("cp.async.wait_group %0;" :: "n"(n) : "memory")

#define LDSM_X4(r0, r1, r2, r3, addr) \
    asm volatile("ldmatrix.sync.aligned.m8n8.x4.shared.b16 {%0,%1,%2,%3}, [%4];" \
        : "=r"(r0), "=r"(r1), "=r"(r2), "=r"(r3) : "r"(addr))

#define MMA_F16(d, a0, a1, a2, a3, b0, b1) \
    asm volatile( \
        "mma.sync.aligned.m16n8k16.row.col.f32.f16.f16.f32 " \
        "{%0,%1,%2,%3}, {%4,%5,%6,%7}, {%8,%9}, {%0,%1,%2,%3};" \
        : "+f"((d)[0]), "+f"((d)[1]), "+f"((d)[2]), "+f"((d)[3]) \
        : "r"(a0), "r"(a1), "r"(a2), "r"(a3), "r"(b0), "r"(b1))

// ===========================================================================
// fp32 -> fp16 conversion
// ===========================================================================
__global__ void cvt_f16(const float* __restrict__ in, __half* __restrict__ out, int n)
{
    int i = (blockIdx.x * blockDim.x + threadIdx.x) * 8;
    if (i < n) {
        float4 a = *(const float4*)(in + i);
        float4 b = *(const float4*)(in + i + 4);
        __half2* o = (__half2*)(out + i);
        o[0] = __floats2half2_rn(a.x, a.y);
        o[1] = __floats2half2_rn(a.z, a.w);
        o[2] = __floats2half2_rn(b.x, b.y);
        o[3] = __floats2half2_rn(b.z, b.w);
    }
}

__global__ void cvt_f16x4(
    const float* __restrict__ i0, __half* __restrict__ o0,
    const float* __restrict__ i1, __half* __restrict__ o1,
    const float* __restrict__ i2, __half* __restrict__ o2,
    const float* __restrict__ i3, __half* __restrict__ o3, int n)
{
    const float* in; __half* out;
    switch (blockIdx.y) {
        case 0: in = i0; out = o0; break;
        case 1: in = i1; out = o1; break;
        case 2: in = i2; out = o2; break;
        default: in = i3; out = o3; break;
    }
    int i = (blockIdx.x * blockDim.x + threadIdx.x) * 8;
    if (i < n) {
        float4 a = *(const float4*)(in + i);
        float4 b = *(const float4*)(in + i + 4);
        __half2* o = (__half2*)(out + i);
        o[0] = __floats2half2_rn(a.x, a.y);
        o[1] = __floats2half2_rn(a.z, a.w);
        o[2] = __floats2half2_rn(b.x, b.y);
        o[3] = __floats2half2_rn(b.z, b.w);
    }
}

// ===========================================================================
// R8-proven GEMM mainloop: CTA 128x128, 256 threads = 8 warps (2M x 4N),
// warp tile 64x32, KC=32, 3-stage cp.async, ONE barrier per chunk.
// acc[4][4][4] = 64 regs. K fixed = DMODEL.
// ===========================================================================
#define KCH 32
#define SAH 40
#define NST 3
#define GSTAGE (128 * SAH)
#define GP_SMEM (2 * NST * GSTAGE * 2)

struct GFrag {
    int wm, wn;
    uint32_t sA0, sB0;
    uint32_t aBase, bBase;
};

__device__ __forceinline__ void gemm_setup(GFrag& f, __half* As, __half* Bs)
{
    const int tid = threadIdx.x;
    const int wid = tid >> 5;
    const int lane = tid & 31;
    f.wm = (wid & 1) * 64;
    f.wn = (wid >> 1) * 32;
    const int lrow = tid >> 1;
    const int lc = (tid & 1) * 2;
    f.sA0 = smem_u32(As) + (lrow * SAH + lc * 8) * 2;
    f.sB0 = smem_u32(Bs) + (lrow * SAH + lc * 8) * 2;
    const int arow = (lane & 7) + ((lane >> 3) & 1) * 8;
    const int acol = (lane >> 4) * 8;
    const int brow = (lane & 7) + (lane >> 4) * 8;
    const int bcol = ((lane >> 3) & 1) * 8;
    f.aBase = smem_u32(As) + ((f.wm + arow) * SAH + acol) * 2;
    f.bBase = smem_u32(Bs) + ((f.wn + brow) * SAH + bcol) * 2;
}

// Ag/Bg: per-thread global pointers (row tid>>1, 32B half tid&1).
__device__ __forceinline__ void gemm_mainloop(
    const GFrag& f, const __half* Ag, const __half* Bg, float acc[4][4][4])
{
#pragma unroll
    for (int i = 0; i < 4; i++)
#pragma unroll
        for (int j = 0; j < 4; j++)
#pragma unroll
            for (int r = 0; r < 4; r++) acc[i][j][r] = 0.0f;

    const uint32_t stB = GSTAGE * 2;
    const int NC = DMODEL / KCH;

#pragma unroll
    for (int c = 0; c < NST - 1; c++) {
        CP16(f.sA0 + c * stB,      Ag + (size_t)c * KCH);
        CP16(f.sA0 + c * stB + 16, Ag + (size_t)c * KCH + 8);
        CP16(f.sB0 + c * stB,      Bg + (size_t)c * KCH);
        CP16(f.sB0 + c * stB + 16, Bg + (size_t)c * KCH + 8);
        CP_COMMIT();
    }

    for (int c = 0; c < NC; c++) {
        const int st = c % NST;
        CP_WAIT(NST - 2);
        __syncthreads();

        {
            const int cn = c + NST - 1;
            if (cn < NC) {
                const int sn = cn % NST;
                CP16(f.sA0 + sn * stB,      Ag + (size_t)cn * KCH);
                CP16(f.sA0 + sn * stB + 16, Ag + (size_t)cn * KCH + 8);
                CP16(f.sB0 + sn * stB,      Bg + (size_t)cn * KCH);
                CP16(f.sB0 + sn * stB + 16, Bg + (size_t)cn * KCH + 8);
            }
            CP_COMMIT();
        }

        const uint32_t aSt = f.aBase + st * stB;
        const uint32_t bSt = f.bBase + st * stB;
#pragma unroll
        for (int ks = 0; ks < 2; ks++) {
            uint32_t a[4][4];
#pragma unroll
            for (int mt = 0; mt < 4; mt++)
                LDSM_X4(a[mt][0], a[mt][1], a[mt][2], a[mt][3],
                        aSt + (mt * 16 * SAH + ks * 16) * 2);
#pragma unroll
            for (int p = 0; p < 2; p++) {
                uint32_t b0, b1, b2, b3;
                LDSM_X4(b0, b1, b2, b3, bSt + (p * 16 * SAH + ks * 16) * 2);
#pragma unroll
                for (int mt = 0; mt < 4; mt++) {
                    MMA_F16(acc[mt][2 * p],     a[mt][0], a[mt][1], a[mt][2], a[mt][3], b0, b1);
                    MMA_F16(acc[mt][2 * p + 1], a[mt][0], a[mt][1], a[mt][2], a[mt][3], b2, b3);
                }
            }
        }
    }
}

// ===========================================================================
// Merged Q/K/V projection, one 1024-CTA launch, 256 threads (R8 config):
//   [0,768):    Q = x @ Wq^T * qscale  (96 m-blocks x 8 n-blocks)
//   [768,896):  K = ctx @ Wk^T         (16 m-blocks x 8 n-blocks)
//   [896,1024): V = ctx @ Wv^T -> [b][h][d][key]
// ===========================================================================
__global__ __launch_bounds__(256) void proj_qkv(
    const __half* __restrict__ xH, const __half* __restrict__ cH,
    const __half* __restrict__ wq, const __half* __restrict__ wk,
    const __half* __restrict__ wv,
    __half* __restrict__ Qo, __half* __restrict__ Ko, __half* __restrict__ Vo,
    float qscale)
{
    extern __shared__ __half sh[];
    __half* As = sh;
    __half* Bs = sh + NST * GSTAGE;

    const int bx = blockIdx.x;
    const int tid = threadIdx.x;
    const int lane = tid & 31;
    const int g = lane >> 2;
    const int t = lane & 3;

    const __half* A;
    const __half* B;
    int bm, bn, job;   // 0=Q, 1=K, 2=V
    if (bx < 768) {
        A = xH; B = wq; bm = (bx >> 3) * 128; bn = (bx & 7) * 128; job = 0;
    } else {
        const int r = bx - 768;
        A = cH; bm = (r >> 4) * 128;
        const int nb = r & 15;
        if (nb < 8) { B = wk; bn = nb * 128; job = 1; }
        else        { B = wv; bn = (nb - 8) * 128; job = 2; }
    }

    GFrag f;
    gemm_setup(f, As, Bs);

    const int lrow = tid >> 1;
    const int lc8 = (tid & 1) * 16;
    float acc[4][4][4];
    gemm_mainloop(f, A + (size_t)(bm + lrow) * DMODEL + lc8,
                     B + (size_t)(bn + lrow) * DMODEL + lc8, acc);

#pragma unroll
    for (int mt = 0; mt < 4; mt++) {
#pragma unroll
        for (int nt = 0; nt < 4; nt++) {
            const int row = bm + f.wm + mt * 16 + g;
            const int col = bn + f.wn + nt * 8 + 2 * t;
            float c0 = acc[mt][nt][0], c1 = acc[mt][nt][1];
            float c2 = acc[mt][nt][2], c3 = acc[mt][nt][3];
            if (job == 0) {
                *(__half2*)&Qo[(size_t)row * DMODEL + col] =
                    __floats2half2_rn(c0 * qscale, c1 * qscale);
                *(__half2*)&Qo[(size_t)(row + 8) * DMODEL + col] =
                    __floats2half2_rn(c2 * qscale, c3 * qscale);
            } else if (job == 1) {
                *(__half2*)&Ko[(size_t)row * DMODEL + col] = __floats2half2_rn(c0, c1);
                *(__half2*)&Ko[(size_t)(row + 8) * DMODEL + col] = __floats2half2_rn(c2, c3);
            } else {
                const int b = row >> 10, key = row & 1023;
                const int h = col >> 6, d = col & 63;
                __half* base = Vo + ((size_t)((b * NHEADS + h) * DHEAD + d)) * SK_TOT;
                base[key]              = __float2half(c0);
                base[SK_TOT + key]     = __float2half(c1);
                base[key + 8]          = __float2half(c2);
                base[SK_TOT + key + 8] = __float2half(c3);
            }
        }
    }
}

// ===========================================================================
// Output projection: out = A @ Wo^T + bias (fp32). Grid (8, 96), 256 thr.
// ===========================================================================
__global__ __launch_bounds__(256) void gemm_out(
    const __half* __restrict__ A, const __half* __restrict__ B,
    float* __restrict__ Cf, const float* __restrict__ bias)
{
    extern __shared__ __half sh[];
    __half* As = sh;
    __half* Bs = sh + NST * GSTAGE;

    const int tid = threadIdx.x;
    const int lane = tid & 31;
    const int g = lane >> 2;
    const int t = lane & 3;
    const int bm = blockIdx.y * 128;
    const int bn = blockIdx.x * 128;

    GFrag f;
    gemm_setup(f, As, Bs);

    const int lrow = tid >> 1;
    const int lc8 = (tid & 1) * 16;
    float acc[4][4][4];
    gemm_mainloop(f, A + (size_t)(bm + lrow) * DMODEL + lc8,
                     B + (size_t)(bn + lrow) * DMODEL + lc8, acc);

#pragma unroll
    for (int mt = 0; mt < 4; mt++) {
#pragma unroll
        for (int nt = 0; nt < 4; nt++) {
            const int row = bm + f.wm + mt * 16 + g;
            const int col = bn + f.wn + nt * 8 + 2 * t;
            float2 bv = *(const float2*)&bias[col];
            *(float2*)&Cf[(size_t)row * DMODEL + col] =
                make_float2(acc[mt][nt][0] + bv.x, acc[mt][nt][1] + bv.y);
            *(float2*)&Cf[(size_t)(row + 8) * DMODEL + col] =
                make_float2(acc[mt][nt][2] + bv.x, acc[mt][nt][3] + bv.y);
        }
    }
}

// ===========================================================================
// Flash attention (unchanged from R8).
// ===========================================================================
#define AS 72
#define NKT (SK_TOT / 64)
#define NBUF 3
#define ATT_SMEM ((128 + 2 * NBUF * 64) * AS * 2)

__global__ __launch_bounds__(256) void attn_f16(
    const __half* __restrict__ Q, const __half* __restrict__ K,
    const __half* __restrict__ V, __half* __restrict__ O)
{
    extern __shared__ __half sma[];
    __half* sQ  = sma;
    __half* sKb = sQ + 128 * AS;
    __half* sVb = sKb + NBUF * 64 * AS;
    const uint32_t bufBytes = 64 * AS * 2;

    const int b = blockIdx.z;
    const int h = blockIdx.y;
    const int qt = blockIdx.x;

    const int tid = threadIdx.x;
    const int wid = tid >> 5;
    const int lane = tid & 31;
    const int g = lane >> 2;
    const int t = lane & 3;

    const uint32_t sQa = smem_u32(sQ);
    const uint32_t sKa = smem_u32(sKb);
    const uint32_t sVa = smem_u32(sVb);

    {
        const int row = tid >> 1, c0 = (tid & 1) * 4;
        const __half* qg = Q + (size_t)(b * SQ_TOT + qt * 128 + row) * DMODEL
                             + h * DHEAD + c0 * 8;
        const uint32_t qd = sQa + (row * AS + c0 * 8) * 2;
#pragma unroll
        for (int i = 0; i < 4; i++) CP16(qd + i * 16, qg + i * 8);
    }

    const int lrow = tid >> 2;
    const int lc = (tid & 3) * 2;
    const __half* kgB = K + (size_t)(b * SK_TOT + lrow) * DMODEL + h * DHEAD + lc * 8;
    const __half* vgB = V + ((size_t)((b * NHEADS + h) * DHEAD + lrow)) * SK_TOT + lc * 8;
    const uint32_t kd0 = sKa + (lrow * AS + lc * 8) * 2;
    const uint32_t vd0 = sVa + (lrow * AS + lc * 8) * 2;

#define ISSUE_KV(kt, buf) do { \
        const __half* kg_ = kgB + (size_t)(kt) * 64 * DMODEL; \
        const __half* vg_ = vgB + (kt) * 64; \
        const uint32_t kd_ = kd0 + (buf) * bufBytes; \
        const uint32_t vd_ = vd0 + (buf) * bufBytes; \
        CP16(kd_, kg_);      CP16(kd_ + 16, kg_ + 8); \
        CP16(vd_, vg_);      CP16(vd_ + 16, vg_ + 8); \
    } while (0)

    ISSUE_KV(0, 0); CP_COMMIT();
    ISSUE_KV(1, 1); CP_COMMIT();

    const int arow = (lane & 7) + ((lane >> 3) & 1) * 8;
    const int acol = (lane >> 4) * 8;
    const int brow = (lane & 7) + (lane >> 4) * 8;
    const int bcol = ((lane >> 3) & 1) * 8;
    const uint32_t aQ = sQa + ((wid * 16 + arow) * AS + acol) * 2;
    const uint32_t bK0 = sKa + (brow * AS + bcol) * 2;
    const uint32_t bV0 = sVa + (brow * AS + bcol) * 2;

    CP_WAIT(1);
    __syncthreads();
    uint32_t qf[4][4];
#pragma unroll
    for (int ks = 0; ks < 4; ks++)
        LDSM_X4(qf[ks][0], qf[ks][1], qf[ks][2], qf[ks][3], aQ + ks * 32);

    float m0 = -1e30f, m1 = -1e30f, l0 = 0.0f, l1 = 0.0f;
    float o[8][4];
#pragma unroll
    for (int dt = 0; dt < 8; dt++)
#pragma unroll
        for (int r = 0; r < 4; r++) o[dt][r] = 0.0f;

    for (int kt = 0; kt < NKT; kt++) {
        if (kt > 0) {
            CP_WAIT(1);
            __syncthreads();
        }
        if (kt + 2 < NKT) ISSUE_KV(kt + 2, (kt + 2) % NBUF);
        CP_COMMIT();

        const uint32_t bOff = (kt % NBUF) * bufBytes;
        const uint32_t bK = bK0 + bOff;
        const uint32_t bV = bV0 + bOff;

        float s[8][4];
#pragma unroll
        for (int nt = 0; nt < 8; nt++)
#pragma unroll
            for (int r = 0; r < 4; r++) s[nt][r] = 0.0f;

#pragma unroll
        for (int ks = 0; ks < 4; ks++) {
#pragma unroll
            for (int p = 0; p < 4; p++) {
                uint32_t b0, b1, b2, b3;
                LDSM_X4(b0, b1, b2, b3, bK + (p * 16 * AS + ks * 16) * 2);
                MMA_F16(s[2 * p],     qf[ks][0], qf[ks][1], qf[ks][2], qf[ks][3], b0, b1);
                MMA_F16(s[2 * p + 1], qf[ks][0], qf[ks][1], qf[ks][2], qf[ks][3], b2, b3);
            }
        }

        float ml0 = -1e30f, ml1 = -1e30f;
#pragma unroll
        for (int nt = 0; nt < 8; nt++) {
            ml0 = fmaxf(ml0, fmaxf(s[nt][0], s[nt][1]));
            ml1 = fmaxf(ml1, fmaxf(s[nt][2], s[nt][3]));
        }
        ml0 = fmaxf(ml0, __shfl_xor_sync(0xffffffffu, ml0, 1));
        ml0 = fmaxf(ml0, __shfl_xor_sync(0xffffffffu, ml0, 2));
        ml1 = fmaxf(ml1, __shfl_xor_sync(0xffffffffu, ml1, 1));
        ml1 = fmaxf(ml1, __shfl_xor_sync(0xffffffffu, ml1, 2));

        const float mn0 = fmaxf(m0, ml0);
        const float mn1 = fmaxf(m1, ml1);
        const float al0 = exp2f(m0 - mn0);
        const float al1 = exp2f(m1 - mn1);
        m0 = mn0; m1 = mn1;

        float rs0 = 0.0f, rs1 = 0.0f;
        uint32_t pa[4][4];
#pragma unroll
        for (int c = 0; c < 4; c++) {
            float p00 = exp2f(s[2 * c][0] - mn0);
            float p01 = exp2f(s[2 * c][1] - mn0);
            float p02 = exp2f(s[2 * c][2] - mn1);
            float p03 = exp2f(s[2 * c][3] - mn1);
            float p10 = exp2f(s[2 * c + 1][0] - mn0);
            float p11 = exp2f(s[2 * c + 1][1] - mn0);
            float p12 = exp2f(s[2 * c + 1][2] - mn1);
            float p13 = exp2f(s[2 * c + 1][3] - mn1);
            rs0 += p00 + p01 + p10 + p11;
            rs1 += p02 + p03 + p12 + p13;
            pa[c][0] = packh2(p00, p01);
            pa[c][1] = packh2(p02, p03);
            pa[c][2] = packh2(p10, p11);
            pa[c][3] = packh2(p12, p13);
        }
        rs0 += __shfl_xor_sync(0xffffffffu, rs0, 1);
        rs0 += __shfl_xor_sync(0xffffffffu, rs0, 2);
        rs1 += __shfl_xor_sync(0xffffffffu, rs1, 1);
        rs1 += __shfl_xor_sync(0xffffffffu, rs1, 2);
        l0 = l0 * al0 + rs0;
        l1 = l1 * al1 + rs1;
#pragma unroll
        for (int dt = 0; dt < 8; dt++) {
            o[dt][0] *= al0; o[dt][1] *= al0;
            o[dt][2] *= al1; o[dt][3] *= al1;
        }

#pragma unroll
        for (int c = 0; c < 4; c++) {
#pragma unroll
            for (int p = 0; p < 4; p++) {
                uint32_t b0, b1, b2, b3;
                LDSM_X4(b0, b1, b2, b3, bV + (p * 16 * AS + c * 16) * 2);
                MMA_F16(o[2 * p],     pa[c][0], pa[c][1], pa[c][2], pa[c][3], b0, b1);
                MMA_F16(o[2 * p + 1], pa[c][0], pa[c][1], pa[c][2], pa[c][3], b2, b3);
            }
        }
    }

    const float inv0 = 1.0f / l0;
    const float inv1 = 1.0f / l1;
    const size_t row0 = (size_t)(b * SQ_TOT + qt * 128 + wid * 16 + g);
    __half* o0 = O + row0 * DMODEL + h * DHEAD + 2 * t;
    __half* o1 = o0 + 8 * DMODEL;
#pragma unroll
    for (int dt = 0; dt < 8; dt++) {
        *(__half2*)(o0 + dt * 8) = __floats2half2_rn(o[dt][0] * inv0, o[dt][1] * inv0);
        *(__half2*)(o1 + dt * 8) = __floats2half2_rn(o[dt][2] * inv1, o[dt][3] * inv1);
    }
}

// ===========================================================================
extern "C" void kernel_launch(void* const* d_in, const int* in_sizes, int n_in,
                              void* d_out, int out_size)
{
    const float* x   = (const float*)d_in[0];
    const float* ctx = (const float*)d_in[1];
    const float* Wq  = (const float*)d_in[2];
    const float* Wk  = (const float*)d_in[3];
    const float* Wv  = (const float*)d_in[4];
    const float* Wo  = (const float*)d_in[5];
    const float* bo  = (const float*)d_in[6];
    float* out = (float*)d_out;

    __half *xH, *cH, *wqH, *wkH, *wvH, *woH, *qh, *kh, *vh, *ah;
    cudaGetSymbolAddress((void**)&xH,  g_xH);
    cudaGetSymbolAddress((void**)&cH,  g_cH);
    cudaGetSymbolAddress((void**)&wqH, g_wqH);
    cudaGetSymbolAddress((void**)&wkH, g_wkH);
    cudaGetSymbolAddress((void**)&wvH, g_wvH);
    cudaGetSymbolAddress((void**)&woH, g_woH);
    cudaGetSymbolAddress((void**)&qh,  g_Qh);
    cudaGetSymbolAddress((void**)&kh,  g_Kh);
    cudaGetSymbolAddress((void**)&vh,  g_Vh);
    cudaGetSymbolAddress((void**)&ah,  g_Ah);

    cudaFuncSetAttribute(proj_qkv,
                         cudaFuncAttributeMaxDynamicSharedMemorySize, GP_SMEM);
    cudaFuncSetAttribute(gemm_out,
                         cudaFuncAttributeMaxDynamicSharedMemorySize, GP_SMEM);
    cudaFuncSetAttribute(attn_f16,
                         cudaFuncAttributeMaxDynamicSharedMemorySize, ATT_SMEM);

    const int M_Q = BATCH * SQ_TOT;   // 12288
    const int M_KV = BATCH * SK_TOT;  // 2048
    const int NW = DMODEL * DMODEL;

    cvt_f16<<<(M_Q * DMODEL / 8 + 255) / 256, 256>>>(x, xH, M_Q * DMODEL);
    cvt_f16<<<(M_KV * DMODEL / 8 + 255) / 256, 256>>>(ctx, cH, M_KV * DMODEL);
    cvt_f16x4<<<dim3((NW / 8 + 255) / 256, 4), 256>>>(
        Wq, wqH, Wk, wkH, Wv, wvH, Wo, woH, NW);

    const float QSCALE = 0.125f * 1.44269504088896341f;  // 1/sqrt(64) * log2(e)

    // merged Q/K/V projection: 768 Q-blocks + 256 KV-blocks, R8 GEMM config
    proj_qkv<<<1024, 256, GP_SMEM>>>(xH, cH, wqH, wkH, wvH, qh, kh, vh, QSCALE);

    attn_f16<<<dim3(SQ_TOT / 128, NHEADS, BATCH), 256, ATT_SMEM>>>(qh, kh, vh, ah);

    gemm_out<<<dim3(8, 96), 256, GP_SMEM>>>(ah, woH, out, bo);
}